// round 2
// baseline (speedup 1.0000x reference)
#include <cuda_runtime.h>
#include <cstdint>

#define NN 2048
#define NBLK 148
#define NTHR 1024
#define NWARP (NTHR / 32)
#define EPSC 1e-10f
#define ITERS 50

// ---------------- device scratch (static allocation, per harness rules) ----
__device__ float g_W[(size_t)NN * NN];   // W[i][j] = exp(-|s_i - a_j|)
__device__ float g_WT[(size_t)NN * NN];  // transpose of W
__device__ float g_lab[NN];
__device__ float g_s[NN];
__device__ float g_E[NN], g_Einv[NN], g_F[NN], g_Finv[NN];
__device__ float g_disc[NN];
__device__ float g_u[NN], g_v[NN];
__device__ float g_part[NN];
__device__ float g_scal[2];  // [0] = idcg
__device__ unsigned g_arrive = 0;
__device__ volatile unsigned g_gen = 0;

// ---------------- grid-wide barrier (all CTAs resident) --------------------
__device__ __forceinline__ void grid_sync() {
    __syncthreads();
    if (threadIdx.x == 0) {
        __threadfence();  // release prior writes to gpu scope
        unsigned gen = g_gen;
        unsigned prev = atomicAdd(&g_arrive, 1u);
        if (prev == gridDim.x - 1) {
            g_arrive = 0;
            __threadfence();
            g_gen = gen + 1;  // volatile store releases everyone
        } else {
            while (g_gen == gen) { __nanosleep(32); }
        }
        __threadfence();  // acquire: gpu-scope fence invalidates L1D
    }
    __syncthreads();
}

// ---------------- warp helpers ---------------------------------------------
__device__ __forceinline__ float warp_sum(float v) {
    #pragma unroll
    for (int o = 16; o; o >>= 1) v += __shfl_xor_sync(0xffffffffu, v, o);
    return v;
}

__global__ void __launch_bounds__(NTHR, 1)
softndcg_kernel(const float* __restrict__ y_pred,
                const float* __restrict__ y_true,
                float* __restrict__ out) {
    const int tid  = threadIdx.x;
    const int lane = tid & 31;
    const int warp = tid >> 5;
    const int gtid = blockIdx.x * NTHR + tid;

    __shared__ float su[NN];        // 8 KB vector staging
    __shared__ float red[NTHR];     // 4 KB reduction
    __shared__ float tile[32][33];  // transpose tile

    // ---- Phase A: elementwise precompute -----------------------------------
    if (gtid < NN) {
        float a = y_pred[gtid];
        float e = expf(a);
        g_E[gtid]    = e;
        g_Einv[gtid] = 1.0f / e;
        g_lab[gtid]  = exp2f(y_true[gtid]) - 1.0f;
        g_disc[gtid] = log2f((float)gtid + 2.0f);
        g_v[gtid]    = 1.0f;
    }
    grid_sync();

    // ---- Phase B: ranks (descending, stable tie-break) ----------------------
    {
        int r = blockIdx.x + NBLK * warp;  // warp-per-element
        if (r < NN) {
            float ai = y_pred[r];
            float li = g_lab[r];
            int cnta = 0, cntl = 0;
            for (int j = lane; j < NN; j += 32) {
                float aj = y_pred[j];
                cnta += (aj > ai) || (aj == ai && j < r);
                float lj = g_lab[j];
                cntl += (lj > li) || (lj == li && j < r);
            }
            #pragma unroll
            for (int o = 16; o; o >>= 1) {
                cnta += __shfl_xor_sync(0xffffffffu, cnta, o);
                cntl += __shfl_xor_sync(0xffffffffu, cntl, o);
            }
            if (lane == 0) {
                g_s[cnta]  = ai;                    // descending-sorted scores
                g_part[r]  = li / g_disc[cntl];     // idcg contribution
            }
        }
    }
    grid_sync();

    // ---- Phase C: F = exp(s); CTA0 reduces idcg -----------------------------
    if (gtid < NN) {
        float s = g_s[gtid];
        float f = expf(s);
        g_F[gtid]    = f;
        g_Finv[gtid] = 1.0f / f;
    }
    if (blockIdx.x == 0) {
        float v = g_part[tid] + g_part[tid + NTHR];
        red[tid] = v;
        __syncthreads();
        #pragma unroll
        for (int s2 = NTHR / 2; s2 > 0; s2 >>= 1) {
            if (tid < s2) red[tid] += red[tid + s2];
            __syncthreads();
        }
        if (tid == 0) g_scal[0] = red[0];
    }
    grid_sync();

    // ---- Phase D: build W and WT (exp-free: min of exp ratios) --------------
    {
        const int ty = warp, tx = lane;
        const int TPD = NN / 32;  // 64 tiles per dim
        for (int t = blockIdx.x; t < TPD * TPD; t += NBLK) {
            int ti = (t / TPD) * 32;
            int tj = (t % TPD) * 32;
            int i = ti + ty, j = tj + tx;
            float w = fminf(g_E[j] * g_Finv[i], g_F[i] * g_Einv[j]);
            g_W[(size_t)i * NN + j] = w;
            tile[ty][tx] = w;
            __syncthreads();
            g_WT[(size_t)(tj + ty) * NN + (ti + tx)] = tile[tx][ty];
            __syncthreads();
        }
    }
    grid_sync();

    // ---- Phase E: u0 = 1 / rowsum(W)  (softmax denominators; row max = 0) ---
    {
        int r = blockIdx.x + NBLK * warp;
        if (r < NN) {
            const float4* rw = reinterpret_cast<const float4*>(g_W + (size_t)r * NN);
            float acc = 0.f;
            #pragma unroll
            for (int k = 0; k < NN / 128; k++) {
                float4 w4 = rw[lane + 32 * k];
                acc += (w4.x + w4.y) + (w4.z + w4.w);
            }
            acc = warp_sum(acc);
            if (lane == 0) g_u[r] = 1.0f / acc;
        }
    }
    grid_sync();

    // ---- Sinkhorn: 50 iterations in scaling-vector form ---------------------
    for (int it = 0; it < ITERS; it++) {
        // column normalize: v <- v / clip(v * (W^T u), EPS)
        for (int i2 = tid; i2 < NN; i2 += NTHR) su[i2] = g_u[i2];
        __syncthreads();
        {
            int r = blockIdx.x + NBLK * warp;
            if (r < NN) {
                const float4* rw = reinterpret_cast<const float4*>(g_WT + (size_t)r * NN);
                const float4* sv = reinterpret_cast<const float4*>(su);
                float acc = 0.f;
                #pragma unroll
                for (int k = 0; k < NN / 128; k++) {
                    float4 w4 = rw[lane + 32 * k];
                    float4 v4 = sv[lane + 32 * k];
                    acc = fmaf(w4.x, v4.x, acc);
                    acc = fmaf(w4.y, v4.y, acc);
                    acc = fmaf(w4.z, v4.z, acc);
                    acc = fmaf(w4.w, v4.w, acc);
                }
                acc = warp_sum(acc);
                if (lane == 0) {
                    float vv = g_v[r];
                    g_v[r] = vv / fmaxf(vv * acc, EPSC);
                }
            }
        }
        grid_sync();

        // row normalize: u <- u / clip(u * (W v), EPS)
        for (int i2 = tid; i2 < NN; i2 += NTHR) su[i2] = g_v[i2];
        __syncthreads();
        {
            int r = blockIdx.x + NBLK * warp;
            if (r < NN) {
                const float4* rw = reinterpret_cast<const float4*>(g_W + (size_t)r * NN);
                const float4* sv = reinterpret_cast<const float4*>(su);
                float acc = 0.f;
                #pragma unroll
                for (int k = 0; k < NN / 128; k++) {
                    float4 w4 = rw[lane + 32 * k];
                    float4 v4 = sv[lane + 32 * k];
                    acc = fmaf(w4.x, v4.x, acc);
                    acc = fmaf(w4.y, v4.y, acc);
                    acc = fmaf(w4.z, v4.z, acc);
                    acc = fmaf(w4.w, v4.w, acc);
                }
                acc = warp_sum(acc);
                if (lane == 0) {
                    float uu = g_u[r];
                    g_u[r] = uu / fmaxf(uu * acc, EPSC);
                }
            }
        }
        grid_sync();
    }

    // ---- Final: dcg_i = u_i * (W (v .* labels))_i / disc_i ------------------
    for (int i2 = tid; i2 < NN; i2 += NTHR) su[i2] = g_v[i2] * g_lab[i2];
    __syncthreads();
    {
        int r = blockIdx.x + NBLK * warp;
        if (r < NN) {
            const float4* rw = reinterpret_cast<const float4*>(g_W + (size_t)r * NN);
            const float4* sv = reinterpret_cast<const float4*>(su);
            float acc = 0.f;
            #pragma unroll
            for (int k = 0; k < NN / 128; k++) {
                float4 w4 = rw[lane + 32 * k];
                float4 v4 = sv[lane + 32 * k];
                acc = fmaf(w4.x, v4.x, acc);
                acc = fmaf(w4.y, v4.y, acc);
                acc = fmaf(w4.z, v4.z, acc);
                acc = fmaf(w4.w, v4.w, acc);
            }
            acc = warp_sum(acc);
            if (lane == 0) g_part[r] = g_u[r] * acc / g_disc[r];
        }
    }
    grid_sync();

    if (blockIdx.x == 0) {
        float v = g_part[tid] + g_part[tid + NTHR];
        red[tid] = v;
        __syncthreads();
        #pragma unroll
        for (int s2 = NTHR / 2; s2 > 0; s2 >>= 1) {
            if (tid < s2) red[tid] += red[tid + s2];
            __syncthreads();
        }
        if (tid == 0) out[0] = 1.0f - red[0] / g_scal[0];
    }
}

extern "C" void kernel_launch(void* const* d_in, const int* in_sizes, int n_in,
                              void* d_out, int out_size) {
    const float* y_pred = (const float*)d_in[0];
    const float* y_true = (const float*)d_in[1];
    float* out = (float*)d_out;
    (void)in_sizes; (void)n_in; (void)out_size;
    softndcg_kernel<<<NBLK, NTHR>>>(y_pred, y_true, out);
}

// round 3
// speedup vs baseline: 3.4575x; 3.4575x over previous
#include <cuda_runtime.h>
#include <cstdint>

#define NN 2048
#define NBLK 148
#define NTHR 1024
#define EPSC 1e-10f
#define ITERS 50
#define TOLC 1e-6f
#define KCH (NN / 128)  // 16 float4-chunks per lane per row

// ---------------- device scratch (static, per harness rules) ---------------
__device__ float g_W[(size_t)NN * NN];   // W[i][j] = exp(-|s_i - a_j|)
__device__ float g_WT[(size_t)NN * NN];  // transpose
__device__ float g_lab[NN], g_s[NN];
__device__ float g_E[NN], g_Einv[NN], g_F[NN], g_Finv[NN];
__device__ float g_disc[NN];
__device__ float g_u[NN], g_v[NN], g_part[NN];
__device__ float g_idcg;
__device__ unsigned g_arrive = 0;
__device__ unsigned g_gen = 0;
__device__ unsigned g_devbits = 0;
__device__ unsigned g_done = 0;

// ---------------- scoped atomics (no CCTL.IVALL — preserve L1D) ------------
__device__ __forceinline__ unsigned ld_acq(const unsigned* p) {
    unsigned v;
    asm volatile("ld.acquire.gpu.u32 %0, [%1];" : "=r"(v) : "l"(p) : "memory");
    return v;
}
__device__ __forceinline__ void st_rel(unsigned* p, unsigned v) {
    asm volatile("st.release.gpu.u32 [%0], %1;" :: "l"(p), "r"(v) : "memory");
}
__device__ __forceinline__ void st_rlx(unsigned* p, unsigned v) {
    asm volatile("st.relaxed.gpu.u32 [%0], %1;" :: "l"(p), "r"(v) : "memory");
}
__device__ __forceinline__ unsigned atom_add_rel(unsigned* p, unsigned v) {
    unsigned o;
    asm volatile("atom.add.release.gpu.u32 %0, [%1], %2;"
                 : "=r"(o) : "l"(p), "r"(v) : "memory");
    return o;
}

// Fence-free grid barrier: release-atomic arrive, acquire-load spin.
// gen is meaningful only in thread 0 of each CTA.
__device__ __forceinline__ void grid_sync(unsigned& gen) {
    __syncthreads();
    if (threadIdx.x == 0) {
        gen++;
        unsigned prev = atom_add_rel(&g_arrive, 1u);
        if (prev == NBLK - 1) {
            st_rlx(&g_arrive, 0u);
            st_rel(&g_gen, gen);
        } else {
            while (ld_acq(&g_gen) != gen) { }
        }
    }
    __syncthreads();
}

__device__ __forceinline__ float warp_sum(float v) {
    #pragma unroll
    for (int o = 16; o; o >>= 1) v += __shfl_xor_sync(0xffffffffu, v, o);
    return v;
}

// warp dot of one 2048-float row with an smem vector.
// STREAM rows use __ldcg so they never evict the L1-resident cached rows.
template <bool STREAM>
__device__ __forceinline__ float dot_row(const float* __restrict__ row,
                                         const float* __restrict__ sv, int lane) {
    const float4* r4 = reinterpret_cast<const float4*>(row);
    const float4* s4 = reinterpret_cast<const float4*>(sv);
    float acc = 0.f;
    #pragma unroll
    for (int k = 0; k < KCH; k++) {
        float4 w = STREAM ? __ldcg(r4 + lane + 32 * k) : r4[lane + 32 * k];
        float4 v = s4[lane + 32 * k];
        acc = fmaf(w.x, v.x, acc);
        acc = fmaf(w.y, v.y, acc);
        acc = fmaf(w.z, v.z, acc);
        acc = fmaf(w.w, v.w, acc);
    }
    return warp_sum(acc);
}

__global__ void __launch_bounds__(NTHR, 1)
softndcg_kernel(const float* __restrict__ y_pred,
                const float* __restrict__ y_true,
                float* __restrict__ out) {
    __shared__ __align__(16) float spool[NN];  // aliased: staging / reduce / tile
    __shared__ float sdev[32];
    __shared__ unsigned sdone;

    const int tid  = threadIdx.x;
    const int lane = tid & 31;
    const int warp = tid >> 5;
    const int bid  = blockIdx.x;
    const int gtid = bid * NTHR + tid;

    unsigned gen = (tid == 0) ? ld_acq(&g_gen) : 0u;  // survive graph replays

    // ---- Phase A: elementwise precompute -----------------------------------
    if (gtid < NN) {
        float a = y_pred[gtid];
        float e = expf(a);
        g_E[gtid]    = e;
        g_Einv[gtid] = 1.0f / e;
        g_lab[gtid]  = exp2f(y_true[gtid]) - 1.0f;
        g_disc[gtid] = log2f((float)gtid + 2.0f);
        g_v[gtid]    = 1.0f;
    }
    if (gtid == 0) { st_rlx(&g_done, 0u); st_rlx(&g_devbits, 0u); }
    grid_sync(gen);

    // ---- Phase B: ranks (descending, stable) -------------------------------
    {
        int r = bid + NBLK * warp;
        if (r < NN) {
            float ai = y_pred[r];
            float li = g_lab[r];
            int ca = 0, cl = 0;
            for (int j = lane; j < NN; j += 32) {
                float aj = y_pred[j];
                ca += (aj > ai) || (aj == ai && j < r);
                float lj = g_lab[j];
                cl += (lj > li) || (lj == li && j < r);
            }
            #pragma unroll
            for (int o = 16; o; o >>= 1) {
                ca += __shfl_xor_sync(0xffffffffu, ca, o);
                cl += __shfl_xor_sync(0xffffffffu, cl, o);
            }
            if (lane == 0) {
                g_s[ca]   = ai;                 // descending-sorted scores
                g_part[r] = li / g_disc[cl];    // idcg contribution
            }
        }
    }
    grid_sync(gen);

    // ---- Phase C: F = exp(s); CTA0 reduces idcg ----------------------------
    if (gtid < NN) {
        float f = expf(g_s[gtid]);
        g_F[gtid]    = f;
        g_Finv[gtid] = 1.0f / f;
    }
    if (bid == 0) {
        float* red = spool;
        red[tid] = g_part[tid] + g_part[tid + NTHR];
        __syncthreads();
        #pragma unroll
        for (int s2 = NTHR / 2; s2 > 0; s2 >>= 1) {
            if (tid < s2) red[tid] += red[tid + s2];
            __syncthreads();
        }
        if (tid == 0) g_idcg = red[0];
    }
    grid_sync(gen);

    // ---- Phase D: build W and WT (exp-free: min of exp ratios) -------------
    {
        float (*tile)[33] = reinterpret_cast<float (*)[33]>(spool);
        const int ty = warp, tx = lane;
        const int TPD = NN / 32;
        for (int t = bid; t < TPD * TPD; t += NBLK) {
            int ti = (t / TPD) * 32;
            int tj = (t % TPD) * 32;
            int i = ti + ty, j = tj + tx;
            float w = fminf(g_E[j] * g_Finv[i], g_F[i] * g_Einv[j]);
            g_W[(size_t)i * NN + j] = w;
            tile[ty][tx] = w;
            __syncthreads();
            g_WT[(size_t)(tj + ty) * NN + (ti + tx)] = tile[tx][ty];
            __syncthreads();
        }
    }
    grid_sync(gen);

    // ---- Phase E: u0 = 1/rowsum(W) (also warms L1 with W rows) -------------
    for (int i2 = tid; i2 < NN; i2 += NTHR) spool[i2] = 1.0f;
    __syncthreads();
    {
        int r = bid + NBLK * warp;
        if (r < NN) {
            float acc = (warp < 13)
                ? dot_row<false>(g_W + (size_t)r * NN, spool, lane)
                : dot_row<true >(g_W + (size_t)r * NN, spool, lane);
            if (lane == 0) g_u[r] = 1.0f / acc;
        }
    }
    grid_sync(gen);

    // ---- Sinkhorn loop (scaling-vector form, early convergence exit) -------
    for (int it = 0; it < ITERS; it++) {
        if (tid == 0) sdone = __ldcg(&g_done);
        __syncthreads();
        if (sdone) break;

        // col step: v <- v / clip(v * (W^T u), EPS); dev check piggybacks
        for (int i2 = tid; i2 < NN; i2 += NTHR) spool[i2] = __ldcg(&g_u[i2]);
        __syncthreads();
        {
            int r = bid + NBLK * warp;
            float dev = 0.f;
            if (r < NN) {
                float acc = (warp < 13)
                    ? dot_row<false>(g_WT + (size_t)r * NN, spool, lane)
                    : dot_row<true >(g_WT + (size_t)r * NN, spool, lane);
                if (lane == 0) {
                    float vv = g_v[r];
                    float cs = vv * acc;                 // col sum of current m
                    dev = fabsf(cs - 1.0f);
                    g_v[r] = vv / fmaxf(cs, EPSC);
                }
            }
            if (lane == 0) sdev[warp] = dev;
        }
        __syncthreads();
        if (tid == 0) {
            float m = 0.f;
            #pragma unroll
            for (int w = 0; w < 32; w++) m = fmaxf(m, sdev[w]);
            atomicMax(&g_devbits, __float_as_uint(m));
        }
        grid_sync(gen);

        // row step: u <- u / clip(u * (W v), EPS)
        if (gtid == 0) {
            unsigned db = __ldcg(&g_devbits);
            if (__uint_as_float(db) < TOLC) st_rlx(&g_done, 1u);
            st_rlx(&g_devbits, 0u);
        }
        for (int i2 = tid; i2 < NN; i2 += NTHR) spool[i2] = __ldcg(&g_v[i2]);
        __syncthreads();
        {
            int r = bid + NBLK * warp;
            if (r < NN) {
                float acc = (warp < 13)
                    ? dot_row<false>(g_W + (size_t)r * NN, spool, lane)
                    : dot_row<true >(g_W + (size_t)r * NN, spool, lane);
                if (lane == 0) {
                    float uu = g_u[r];
                    g_u[r] = uu / fmaxf(uu * acc, EPSC);
                }
            }
        }
        grid_sync(gen);
    }

    // ---- Final: dcg_i = u_i * (W (v .* lab))_i / disc_i --------------------
    for (int i2 = tid; i2 < NN; i2 += NTHR)
        spool[i2] = __ldcg(&g_v[i2]) * g_lab[i2];
    __syncthreads();
    {
        int r = bid + NBLK * warp;
        if (r < NN) {
            float acc = (warp < 13)
                ? dot_row<false>(g_W + (size_t)r * NN, spool, lane)
                : dot_row<true >(g_W + (size_t)r * NN, spool, lane);
            if (lane == 0) g_part[r] = g_u[r] * acc / g_disc[r];
        }
    }
    grid_sync(gen);

    if (bid == 0) {
        float v = __ldcg(&g_part[tid]) + __ldcg(&g_part[tid + NTHR]);
        __syncthreads();
        float* red = spool;
        red[tid] = v;
        __syncthreads();
        #pragma unroll
        for (int s2 = NTHR / 2; s2 > 0; s2 >>= 1) {
            if (tid < s2) red[tid] += red[tid + s2];
            __syncthreads();
        }
        if (tid == 0) out[0] = 1.0f - red[0] / g_idcg;
    }
}

extern "C" void kernel_launch(void* const* d_in, const int* in_sizes, int n_in,
                              void* d_out, int out_size) {
    const float* y_pred = (const float*)d_in[0];
    const float* y_true = (const float*)d_in[1];
    float* out = (float*)d_out;
    (void)in_sizes; (void)n_in; (void)out_size;
    softndcg_kernel<<<NBLK, NTHR>>>(y_pred, y_true, out);
}